// round 6
// baseline (speedup 1.0000x reference)
#include <cuda_runtime.h>
#include <math.h>

// Problem constants (fixed by the reference)
#define TT   4096   // tokens = B*S
#define DD   1024   // embed dim
#define EE   16     // experts
#define CC   512    // capacity = T*2/E
#define II   4096   // expert intermediate
#define IIS  2048   // shared intermediate

#define BK   16     // k-tile (fp32 elements)
#define AST  20     // smem row stride in floats (bank-conflict-free)

// ---------------- scratch (static device globals; no allocs allowed) -------
__device__ __align__(16) float g_scores[EE * TT];
__device__ int   g_tidx[EE * CC];
__device__ float g_tw  [EE * CC];
__device__ __align__(16) float g_xg[(size_t)EE * CC * DD];   // gathered tokens (rounded)
__device__ __align__(16) float g_H [(size_t)EE * CC * II];   // expert hidden   (rounded)
__device__ __align__(16) float g_Hs[(size_t)TT * IIS];       // shared hidden   (rounded)
__device__ __align__(16) float g_xc[(size_t)TT * DD];        // rounded x
// tf32-RNA-rounded weight copies
__device__ __align__(16) float g_Wgc[(size_t)EE * II * DD];
__device__ __align__(16) float g_Wuc[(size_t)EE * II * DD];
__device__ __align__(16) float g_Wdc[(size_t)EE * DD * II];
__device__ __align__(16) float g_Sgc[(size_t)IIS * DD];
__device__ __align__(16) float g_Suc[(size_t)IIS * DD];
__device__ __align__(16) float g_Sdc[(size_t)DD * IIS];

// ---------------- helpers --------------------------------------------------
__device__ __forceinline__ float f2tff(float x) {
    unsigned u; asm("cvt.rna.tf32.f32 %0, %1;" : "=r"(u) : "f"(x));
    return __uint_as_float(u);
}

__device__ __forceinline__ void mma_tf32(float* d, const unsigned* a, const unsigned* b,
                                         const float* c) {
    asm volatile(
        "mma.sync.aligned.m16n8k8.row.col.f32.tf32.tf32.f32 "
        "{%0,%1,%2,%3},{%4,%5,%6,%7},{%8,%9},{%10,%11,%12,%13};"
        : "=f"(d[0]), "=f"(d[1]), "=f"(d[2]), "=f"(d[3])
        : "r"(a[0]), "r"(a[1]), "r"(a[2]), "r"(a[3]),
          "r"(b[0]), "r"(b[1]),
          "f"(c[0]), "f"(c[1]), "f"(c[2]), "f"(c[3]));
}

__device__ __forceinline__ void cpa16(void* dst, const void* src) {
    unsigned s = (unsigned)__cvta_generic_to_shared(dst);
    asm volatile("cp.async.cg.shared.global [%0], [%1], 16;" :: "r"(s), "l"(src));
}
__device__ __forceinline__ void cpa_commit() { asm volatile("cp.async.commit_group;"); }
__device__ __forceinline__ void cpa_wait1()  { asm volatile("cp.async.wait_group 1;"); }

__device__ __forceinline__ float gelu_exact(float g) {
    return 0.5f * g * (1.f + erff(g * 0.70710678118654752f));
}

// ---------------- tf32-rounding copy ---------------------------------------
__global__ void k_cvt(const float4* __restrict__ s, float4* __restrict__ d, int n) {
    for (int i = blockIdx.x * blockDim.x + threadIdx.x; i < n; i += gridDim.x * blockDim.x) {
        float4 v = s[i];
        v.x = f2tff(v.x); v.y = f2tff(v.y); v.z = f2tff(v.z); v.w = f2tff(v.w);
        d[i] = v;
    }
}

// ---------------- 1) gating: logits + softmax ------------------------------
__global__ void k_gate(const float* __restrict__ x, const float* __restrict__ gw) {
    int t = blockIdx.x;
    __shared__ float xs[DD];
    __shared__ float lg[EE];
    int tid = threadIdx.x;                 // 128 threads
    for (int k = tid; k < DD; k += 128) xs[k] = x[(size_t)t * DD + k];
    __syncthreads();
    int w = tid >> 5, lane = tid & 31;
    for (int e = w * 4; e < w * 4 + 4; e++) {
        const float* g = gw + (size_t)e * DD;
        float s = 0.f;
        for (int k = lane; k < DD; k += 32) s += xs[k] * g[k];
        for (int o = 16; o; o >>= 1) s += __shfl_down_sync(0xffffffffu, s, o);
        if (!lane) lg[e] = s;
    }
    __syncthreads();
    if (tid == 0) {
        float m = lg[0];
        for (int e = 1; e < EE; e++) m = fmaxf(m, lg[e]);
        float ex[EE]; float sum = 0.f;
        for (int e = 0; e < EE; e++) { ex[e] = expf(lg[e] - m); sum += ex[e]; }
        float inv = 1.f / sum;
        for (int e = 0; e < EE; e++) g_scores[(size_t)e * TT + t] = ex[e] * inv;
    }
}

// ---------------- 2) per-expert top-C via bitonic sort ---------------------
__global__ void k_topk() {
    int e = blockIdx.x;
    __shared__ float v[TT];
    __shared__ int   ix[TT];
    int tid = threadIdx.x;                 // 512 threads
    for (int i = tid; i < TT; i += 512) { v[i] = g_scores[(size_t)e * TT + i]; ix[i] = i; }
    __syncthreads();
    for (int k = 2; k <= TT; k <<= 1) {
        for (int j = k >> 1; j > 0; j >>= 1) {
            for (int i = tid; i < TT; i += 512) {
                int p = i ^ j;
                if (p > i) {
                    bool desc = ((i & k) == 0);
                    float a = v[i], b = v[p];
                    if (desc ? (a < b) : (a > b)) {
                        v[i] = b; v[p] = a; int q = ix[i]; ix[i] = ix[p]; ix[p] = q;
                    }
                }
            }
            __syncthreads();
        }
    }
    for (int c = tid; c < CC; c += 512) { g_tidx[e * CC + c] = ix[c]; g_tw[e * CC + c] = v[c]; }
}

// ---------------- 3) gather selected tokens (rounded) ----------------------
__global__ void k_gather(const float4* __restrict__ x4) {
    int gid = blockIdx.x * blockDim.x + threadIdx.x;
    if (gid >= EE * CC * (DD / 4)) return;
    int q = gid & (DD / 4 - 1);
    int r = gid >> 8;
    float4 v = x4[(size_t)g_tidx[r] * (DD / 4) + q];
    v.x = f2tff(v.x); v.y = f2tff(v.y); v.z = f2tff(v.z); v.w = f2tff(v.w);
    reinterpret_cast<float4*>(g_xg)[gid] = v;
}

// ---------------- 4) dual NT-GEMM (tf32 HMMA, pre-rounded) + GELU ----------
// H = gelu(A @ Bg^T) * (A @ Bu^T).  A:(M,K) rm, B*:(N,K) rm. All pre-rounded.
// Block tile 128x64, warps 2x4, warp tile 64x16. No cvt in inner loop.
__global__ __launch_bounds__(256, 2) void k_mlp_in_tc(
    const float* __restrict__ A0, const float* __restrict__ Bg0,
    const float* __restrict__ Bu0, float* __restrict__ H0,
    int M, int N, int K, long sA, long sB, long sH)
{
    __shared__ float As[2][128][AST];
    __shared__ float Gs[2][64][AST];
    __shared__ float Us[2][64][AST];

    int e = blockIdx.z;
    const float* A  = A0  + (size_t)e * sA;
    const float* Bg = Bg0 + (size_t)e * sB;
    const float* Bu = Bu0 + (size_t)e * sB;
    float*       H  = H0  + (size_t)e * sH;

    int m0 = blockIdx.y * 128, n0 = blockIdx.x * 64;
    int tid = threadIdx.x, lane = tid & 31, warp = tid >> 5;
    int mo = (warp & 1) * 64, no = (warp >> 1) * 16;

    float accG[4][2][4] = {{{0}}}, accU[4][2][4] = {{{0}}};

    int ar = tid >> 2, aq = (tid & 3) * 4;
    int iters = K / BK;

    {
        cpa16(&As[0][ar][aq],      A  + (size_t)(m0 + ar) * K + aq);
        cpa16(&As[0][ar + 64][aq], A  + (size_t)(m0 + ar + 64) * K + aq);
        cpa16(&Gs[0][ar][aq],      Bg + (size_t)(n0 + ar) * K + aq);
        cpa16(&Us[0][ar][aq],      Bu + (size_t)(n0 + ar) * K + aq);
    }
    cpa_commit();

    for (int it = 0; it < iters; it++) {
        int st = it & 1;
        if (it + 1 < iters) {
            int ns = 1 - st;
            long k0 = (long)(it + 1) * BK;
            cpa16(&As[ns][ar][aq],      A  + (size_t)(m0 + ar) * K + k0 + aq);
            cpa16(&As[ns][ar + 64][aq], A  + (size_t)(m0 + ar + 64) * K + k0 + aq);
            cpa16(&Gs[ns][ar][aq],      Bg + (size_t)(n0 + ar) * K + k0 + aq);
            cpa16(&Us[ns][ar][aq],      Bu + (size_t)(n0 + ar) * K + k0 + aq);
        }
        cpa_commit();
        cpa_wait1();
        __syncthreads();

#pragma unroll
        for (int ks = 0; ks < BK; ks += 8) {
            unsigned af[4][4];
#pragma unroll
            for (int mi = 0; mi < 4; mi++) {
                int r = mo + mi * 16 + (lane >> 2);
                int c = ks + (lane & 3);
                af[mi][0] = __float_as_uint(As[st][r][c]);
                af[mi][1] = __float_as_uint(As[st][r + 8][c]);
                af[mi][2] = __float_as_uint(As[st][r][c + 4]);
                af[mi][3] = __float_as_uint(As[st][r + 8][c + 4]);
            }
#pragma unroll
            for (int ni = 0; ni < 2; ni++) {
                int bn = no + ni * 8 + (lane >> 2);
                int c = ks + (lane & 3);
                unsigned bg[2], bu[2];
                bg[0] = __float_as_uint(Gs[st][bn][c]);
                bg[1] = __float_as_uint(Gs[st][bn][c + 4]);
                bu[0] = __float_as_uint(Us[st][bn][c]);
                bu[1] = __float_as_uint(Us[st][bn][c + 4]);
#pragma unroll
                for (int mi = 0; mi < 4; mi++) {
                    mma_tf32(accG[mi][ni], af[mi], bg, accG[mi][ni]);
                    mma_tf32(accU[mi][ni], af[mi], bu, accU[mi][ni]);
                }
            }
        }
        __syncthreads();
    }

    // epilogue: h = round_tf32(gelu(g) * u)  (H is the A operand of down GEMM)
#pragma unroll
    for (int mi = 0; mi < 4; mi++) {
        int r0 = m0 + mo + mi * 16 + (lane >> 2);
#pragma unroll
        for (int ni = 0; ni < 2; ni++) {
            int col = n0 + no + ni * 8 + (lane & 3) * 2;
            float* p0 = H + (size_t)r0 * N + col;
            float* p1 = H + (size_t)(r0 + 8) * N + col;
            p0[0] = f2tff(gelu_exact(accG[mi][ni][0]) * accU[mi][ni][0]);
            p0[1] = f2tff(gelu_exact(accG[mi][ni][1]) * accU[mi][ni][1]);
            p1[0] = f2tff(gelu_exact(accG[mi][ni][2]) * accU[mi][ni][2]);
            p1[1] = f2tff(gelu_exact(accG[mi][ni][3]) * accU[mi][ni][3]);
        }
    }
}

// ---------------- 5) NT-GEMM down-proj (pre-rounded), store or scatter -----
__global__ __launch_bounds__(256, 2) void k_mlp_out_tc(
    const float* __restrict__ A0, const float* __restrict__ B0,
    float* __restrict__ out, int M, int N, int K, long sA, long sB,
    const int* __restrict__ tidx, const float* __restrict__ tw)
{
    __shared__ float As[2][128][AST];
    __shared__ float Bs[2][128][AST];

    int e = blockIdx.z;
    const float* A = A0 + (size_t)e * sA;
    const float* B = B0 + (size_t)e * sB;

    int m0 = blockIdx.y * 128, n0 = blockIdx.x * 128;
    int tid = threadIdx.x, lane = tid & 31, warp = tid >> 5;
    int mo = (warp & 1) * 64, no = (warp >> 1) * 32;

    float acc[4][4][4] = {{{0}}};

    int ar = tid >> 2, aq = (tid & 3) * 4;
    int iters = K / BK;

    {
        cpa16(&As[0][ar][aq],      A + (size_t)(m0 + ar) * K + aq);
        cpa16(&As[0][ar + 64][aq], A + (size_t)(m0 + ar + 64) * K + aq);
        cpa16(&Bs[0][ar][aq],      B + (size_t)(n0 + ar) * K + aq);
        cpa16(&Bs[0][ar + 64][aq], B + (size_t)(n0 + ar + 64) * K + aq);
    }
    cpa_commit();

    for (int it = 0; it < iters; it++) {
        int st = it & 1;
        if (it + 1 < iters) {
            int ns = 1 - st;
            long k0 = (long)(it + 1) * BK;
            cpa16(&As[ns][ar][aq],      A + (size_t)(m0 + ar) * K + k0 + aq);
            cpa16(&As[ns][ar + 64][aq], A + (size_t)(m0 + ar + 64) * K + k0 + aq);
            cpa16(&Bs[ns][ar][aq],      B + (size_t)(n0 + ar) * K + k0 + aq);
            cpa16(&Bs[ns][ar + 64][aq], B + (size_t)(n0 + ar + 64) * K + k0 + aq);
        }
        cpa_commit();
        cpa_wait1();
        __syncthreads();

#pragma unroll
        for (int ks = 0; ks < BK; ks += 8) {
            unsigned af[4][4];
#pragma unroll
            for (int mi = 0; mi < 4; mi++) {
                int r = mo + mi * 16 + (lane >> 2);
                int c = ks + (lane & 3);
                af[mi][0] = __float_as_uint(As[st][r][c]);
                af[mi][1] = __float_as_uint(As[st][r + 8][c]);
                af[mi][2] = __float_as_uint(As[st][r][c + 4]);
                af[mi][3] = __float_as_uint(As[st][r + 8][c + 4]);
            }
#pragma unroll
            for (int ni = 0; ni < 4; ni++) {
                int bn = no + ni * 8 + (lane >> 2);
                int c = ks + (lane & 3);
                unsigned bf[2];
                bf[0] = __float_as_uint(Bs[st][bn][c]);
                bf[1] = __float_as_uint(Bs[st][bn][c + 4]);
#pragma unroll
                for (int mi = 0; mi < 4; mi++)
                    mma_tf32(acc[mi][ni], af[mi], bf, acc[mi][ni]);
            }
        }
        __syncthreads();
    }

    if (tidx) {
#pragma unroll
        for (int mi = 0; mi < 4; mi++) {
            int mA = m0 + mo + mi * 16 + (lane >> 2);
            int mB = mA + 8;
            int tokA = tidx[e * CC + mA]; float wA = tw[e * CC + mA];
            int tokB = tidx[e * CC + mB]; float wB = tw[e * CC + mB];
#pragma unroll
            for (int ni = 0; ni < 4; ni++) {
                int col = n0 + no + ni * 8 + (lane & 3) * 2;
                atomicAdd(&out[(size_t)tokA * N + col],     acc[mi][ni][0] * wA);
                atomicAdd(&out[(size_t)tokA * N + col + 1], acc[mi][ni][1] * wA);
                atomicAdd(&out[(size_t)tokB * N + col],     acc[mi][ni][2] * wB);
                atomicAdd(&out[(size_t)tokB * N + col + 1], acc[mi][ni][3] * wB);
            }
        }
    } else {
#pragma unroll
        for (int mi = 0; mi < 4; mi++) {
            int r0 = m0 + mo + mi * 16 + (lane >> 2);
#pragma unroll
            for (int ni = 0; ni < 4; ni++) {
                int col = n0 + no + ni * 8 + (lane & 3) * 2;
                float* p0 = out + (size_t)r0 * N + col;
                float* p1 = out + (size_t)(r0 + 8) * N + col;
                p0[0] = acc[mi][ni][0]; p0[1] = acc[mi][ni][1];
                p1[0] = acc[mi][ni][2]; p1[1] = acc[mi][ni][3];
            }
        }
    }
}

// ---------------- launch ---------------------------------------------------
extern "C" void kernel_launch(void* const* d_in, const int* in_sizes, int n_in,
                              void* d_out, int out_size) {
    const float* x  = (const float*)d_in[0];
    const float* gw = (const float*)d_in[1];
    const float* Wg = (const float*)d_in[2];
    const float* Wu = (const float*)d_in[3];
    const float* Wd = (const float*)d_in[4];
    const float* Sg = (const float*)d_in[5];
    const float* Su = (const float*)d_in[6];
    const float* Sd = (const float*)d_in[7];
    float* out = (float*)d_out;

    float *xg, *H, *Hs, *xc, *tw;
    float *Wgc, *Wuc, *Wdc, *Sgc, *Suc, *Sdc;
    int* tidx;
    cudaGetSymbolAddress((void**)&xg,   g_xg);
    cudaGetSymbolAddress((void**)&H,    g_H);
    cudaGetSymbolAddress((void**)&Hs,   g_Hs);
    cudaGetSymbolAddress((void**)&xc,   g_xc);
    cudaGetSymbolAddress((void**)&tidx, g_tidx);
    cudaGetSymbolAddress((void**)&tw,   g_tw);
    cudaGetSymbolAddress((void**)&Wgc,  g_Wgc);
    cudaGetSymbolAddress((void**)&Wuc,  g_Wuc);
    cudaGetSymbolAddress((void**)&Wdc,  g_Wdc);
    cudaGetSymbolAddress((void**)&Sgc,  g_Sgc);
    cudaGetSymbolAddress((void**)&Suc,  g_Suc);
    cudaGetSymbolAddress((void**)&Sdc,  g_Sdc);

    // round weights + x into tf32-RNA copies (once per launch)
    k_cvt<<<2048, 256>>>((const float4*)Wg, (float4*)Wgc, EE * II * DD / 4);
    k_cvt<<<2048, 256>>>((const float4*)Wu, (float4*)Wuc, EE * II * DD / 4);
    k_cvt<<<2048, 256>>>((const float4*)Wd, (float4*)Wdc, EE * DD * II / 4);
    k_cvt<<<512, 256>>>((const float4*)Sg, (float4*)Sgc, IIS * DD / 4);
    k_cvt<<<512, 256>>>((const float4*)Su, (float4*)Suc, IIS * DD / 4);
    k_cvt<<<512, 256>>>((const float4*)Sd, (float4*)Sdc, DD * IIS / 4);
    k_cvt<<<512, 256>>>((const float4*)x,  (float4*)xc,  TT * DD / 4);

    k_gate<<<TT, 128>>>(x, gw);
    k_topk<<<EE, 512>>>();
    k_gather<<<(EE * CC * (DD / 4) + 255) / 256, 256>>>((const float4*)x);

    // expert gate/up + gelu  (M=C, N=I, K=D), batched over experts
    dim3 g1(II / 64, CC / 128, EE);
    k_mlp_in_tc<<<g1, 256>>>(xg, Wgc, Wuc, H, CC, II, DD,
                             (long)CC * DD, (long)II * DD, (long)CC * II);
    // shared gate/up + gelu  (M=T, N=IS, K=D)
    dim3 g2(IIS / 64, TT / 128, 1);
    k_mlp_in_tc<<<g2, 256>>>(xc, Sgc, Suc, Hs, TT, IIS, DD, 0, 0, 0);

    // shared down-proj: fully initializes out  (M=T, N=D, K=IS)
    dim3 g3(DD / 128, TT / 128, 1);
    k_mlp_out_tc<<<g3, 256>>>(Hs, Sdc, out, TT, DD, IIS, 0, 0, nullptr, nullptr);
    // expert down-proj + weighted scatter-add  (M=C, N=D, K=I)
    dim3 g4(DD / 128, CC / 128, EE);
    k_mlp_out_tc<<<g4, 256>>>(H, Wdc, out, CC, DD, II,
                              (long)CC * II, (long)DD * II, tidx, tw);
}

// round 7
// speedup vs baseline: 1.0759x; 1.0759x over previous
#include <cuda_runtime.h>
#include <math.h>

// Problem constants (fixed by the reference)
#define TT   4096   // tokens = B*S
#define DD   1024   // embed dim
#define EE   16     // experts
#define CC   512    // capacity = T*2/E
#define II   4096   // expert intermediate
#define IIS  2048   // shared intermediate

#define BK   16     // k-tile (fp32 elements)
#define AST  20     // smem row stride in floats (bank-conflict-free)
#define NSTG 3      // cp.async pipeline stages

// dynamic smem: in-kernel  As[3][128][20] + Gs[3][64][20] + Us[3][64][20]
//               down-kernel As[3][128][20] + Bs[3][128][20]
#define SM_IN_BYTES  ((NSTG*128*AST + NSTG*64*AST + NSTG*64*AST) * 4)   // 61440
#define SM_DN_BYTES  ((NSTG*128*AST + NSTG*128*AST) * 4)                // 61440

// ---------------- scratch (static device globals; no allocs allowed) -------
__device__ __align__(16) float g_scores[EE * TT];
__device__ int   g_tidx[EE * CC];
__device__ float g_tw  [EE * CC];
__device__ __align__(16) float g_xg[(size_t)EE * CC * DD];   // gathered tokens
__device__ __align__(16) float g_H [(size_t)EE * CC * II];   // expert hidden
__device__ __align__(16) float g_Hs[(size_t)TT * IIS];       // shared hidden

// ---------------- helpers --------------------------------------------------
__device__ __forceinline__ unsigned f2tf(float x) {
    unsigned r;
    asm("cvt.rna.tf32.f32 %0, %1;" : "=r"(r) : "f"(x));
    return r;
}

__device__ __forceinline__ void mma_tf32(float* d, const unsigned* a, const unsigned* b,
                                         const float* c) {
    asm volatile(
        "mma.sync.aligned.m16n8k8.row.col.f32.tf32.tf32.f32 "
        "{%0,%1,%2,%3},{%4,%5,%6,%7},{%8,%9},{%10,%11,%12,%13};"
        : "=f"(d[0]), "=f"(d[1]), "=f"(d[2]), "=f"(d[3])
        : "r"(a[0]), "r"(a[1]), "r"(a[2]), "r"(a[3]),
          "r"(b[0]), "r"(b[1]),
          "f"(c[0]), "f"(c[1]), "f"(c[2]), "f"(c[3]));
}

__device__ __forceinline__ void cpa16(void* dst, const void* src) {
    unsigned s = (unsigned)__cvta_generic_to_shared(dst);
    asm volatile("cp.async.cg.shared.global [%0], [%1], 16;" :: "r"(s), "l"(src));
}
__device__ __forceinline__ void cpa_commit() { asm volatile("cp.async.commit_group;"); }
__device__ __forceinline__ void cpa_wait1()  { asm volatile("cp.async.wait_group 1;"); }

__device__ __forceinline__ float gelu_exact(float g) {
    return 0.5f * g * (1.f + erff(g * 0.70710678118654752f));
}

// ---------------- 1) gating: logits + softmax ------------------------------
__global__ void k_gate(const float* __restrict__ x, const float* __restrict__ gw) {
    int t = blockIdx.x;
    __shared__ float xs[DD];
    __shared__ float lg[EE];
    int tid = threadIdx.x;                 // 128 threads
    for (int k = tid; k < DD; k += 128) xs[k] = x[(size_t)t * DD + k];
    __syncthreads();
    int w = tid >> 5, lane = tid & 31;
    for (int e = w * 4; e < w * 4 + 4; e++) {
        const float* g = gw + (size_t)e * DD;
        float s = 0.f;
        for (int k = lane; k < DD; k += 32) s += xs[k] * g[k];
        for (int o = 16; o; o >>= 1) s += __shfl_down_sync(0xffffffffu, s, o);
        if (!lane) lg[e] = s;
    }
    __syncthreads();
    if (tid == 0) {
        float m = lg[0];
        for (int e = 1; e < EE; e++) m = fmaxf(m, lg[e]);
        float ex[EE]; float sum = 0.f;
        for (int e = 0; e < EE; e++) { ex[e] = expf(lg[e] - m); sum += ex[e]; }
        float inv = 1.f / sum;
        for (int e = 0; e < EE; e++) g_scores[(size_t)e * TT + t] = ex[e] * inv;
    }
}

// ---------------- 2) per-expert top-C via bitonic sort ---------------------
__global__ void k_topk() {
    int e = blockIdx.x;
    __shared__ float v[TT];
    __shared__ int   ix[TT];
    int tid = threadIdx.x;                 // 512 threads
    for (int i = tid; i < TT; i += 512) { v[i] = g_scores[(size_t)e * TT + i]; ix[i] = i; }
    __syncthreads();
    for (int k = 2; k <= TT; k <<= 1) {
        for (int j = k >> 1; j > 0; j >>= 1) {
            for (int i = tid; i < TT; i += 512) {
                int p = i ^ j;
                if (p > i) {
                    bool desc = ((i & k) == 0);
                    float a = v[i], b = v[p];
                    if (desc ? (a < b) : (a > b)) {
                        v[i] = b; v[p] = a; int q = ix[i]; ix[i] = ix[p]; ix[p] = q;
                    }
                }
            }
            __syncthreads();
        }
    }
    for (int c = tid; c < CC; c += 512) { g_tidx[e * CC + c] = ix[c]; g_tw[e * CC + c] = v[c]; }
}

// ---------------- 3) gather selected tokens --------------------------------
__global__ void k_gather(const float4* __restrict__ x4) {
    int gid = blockIdx.x * blockDim.x + threadIdx.x;
    if (gid >= EE * CC * (DD / 4)) return;
    int q = gid & (DD / 4 - 1);
    int r = gid >> 8;
    int tok = g_tidx[r];
    reinterpret_cast<float4*>(g_xg)[gid] = x4[(size_t)tok * (DD / 4) + q];
}

// ---------------- 4) dual NT-GEMM (tf32 HMMA) + exact GELU gate ------------
// H = gelu(A @ Bg^T) * (A @ Bu^T).  Block tile 128x64, warps 2x4 (64x16 each).
// 3-stage cp.async ring, ONE __syncthreads per k-tile.
__global__ __launch_bounds__(256, 2) void k_mlp_in_tc(
    const float* __restrict__ A0, const float* __restrict__ Bg0,
    const float* __restrict__ Bu0, float* __restrict__ H0,
    int M, int N, int K, long sA, long sB, long sH)
{
    extern __shared__ float sm[];
    float (*As)[128][AST] = (float(*)[128][AST])sm;
    float (*Gs)[64][AST]  = (float(*)[64][AST])(sm + NSTG * 128 * AST);
    float (*Us)[64][AST]  = (float(*)[64][AST])(sm + NSTG * 128 * AST + NSTG * 64 * AST);

    int e = blockIdx.z;
    const float* A  = A0  + (size_t)e * sA;
    const float* Bg = Bg0 + (size_t)e * sB;
    const float* Bu = Bu0 + (size_t)e * sB;
    float*       H  = H0  + (size_t)e * sH;

    int m0 = blockIdx.y * 128, n0 = blockIdx.x * 64;
    int tid = threadIdx.x, lane = tid & 31, warp = tid >> 5;
    int mo = (warp & 1) * 64, no = (warp >> 1) * 16;

    float accG[4][2][4] = {{{0}}}, accU[4][2][4] = {{{0}}};

    int ar = tid >> 2, aq = (tid & 3) * 4;
    int iters = K / BK;

#define STAGE_IN(slot, kq0)                                                      \
    do {                                                                         \
        long _k = (kq0);                                                         \
        cpa16(&As[slot][ar][aq],      A  + (size_t)(m0 + ar) * K + _k + aq);     \
        cpa16(&As[slot][ar + 64][aq], A  + (size_t)(m0 + ar + 64) * K + _k + aq);\
        cpa16(&Gs[slot][ar][aq],      Bg + (size_t)(n0 + ar) * K + _k + aq);     \
        cpa16(&Us[slot][ar][aq],      Bu + (size_t)(n0 + ar) * K + _k + aq);     \
    } while (0)

    STAGE_IN(0, 0);  cpa_commit();
    STAGE_IN(1, BK); cpa_commit();

    for (int it = 0; it < iters; it++) {
        int st = it % NSTG;
        cpa_wait1();
        __syncthreads();
        if (it + 2 < iters) STAGE_IN((it + 2) % NSTG, (long)(it + 2) * BK);
        cpa_commit();

#pragma unroll
        for (int ks = 0; ks < BK; ks += 8) {
            unsigned af[4][4];
#pragma unroll
            for (int mi = 0; mi < 4; mi++) {
                int r = mo + mi * 16 + (lane >> 2);
                int c = ks + (lane & 3);
                af[mi][0] = f2tf(As[st][r][c]);
                af[mi][1] = f2tf(As[st][r + 8][c]);
                af[mi][2] = f2tf(As[st][r][c + 4]);
                af[mi][3] = f2tf(As[st][r + 8][c + 4]);
            }
#pragma unroll
            for (int ni = 0; ni < 2; ni++) {
                int bn = no + ni * 8 + (lane >> 2);
                int c = ks + (lane & 3);
                unsigned bg[2], bu[2];
                bg[0] = f2tf(Gs[st][bn][c]); bg[1] = f2tf(Gs[st][bn][c + 4]);
                bu[0] = f2tf(Us[st][bn][c]); bu[1] = f2tf(Us[st][bn][c + 4]);
#pragma unroll
                for (int mi = 0; mi < 4; mi++) {
                    mma_tf32(accG[mi][ni], af[mi], bg, accG[mi][ni]);
                    mma_tf32(accU[mi][ni], af[mi], bu, accU[mi][ni]);
                }
            }
        }
    }
#undef STAGE_IN

    // epilogue: h = gelu(g) * u
#pragma unroll
    for (int mi = 0; mi < 4; mi++) {
        int r0 = m0 + mo + mi * 16 + (lane >> 2);
#pragma unroll
        for (int ni = 0; ni < 2; ni++) {
            int col = n0 + no + ni * 8 + (lane & 3) * 2;
            float* p0 = H + (size_t)r0 * N + col;
            float* p1 = H + (size_t)(r0 + 8) * N + col;
            p0[0] = gelu_exact(accG[mi][ni][0]) * accU[mi][ni][0];
            p0[1] = gelu_exact(accG[mi][ni][1]) * accU[mi][ni][1];
            p1[0] = gelu_exact(accG[mi][ni][2]) * accU[mi][ni][2];
            p1[1] = gelu_exact(accG[mi][ni][3]) * accU[mi][ni][3];
        }
    }
}

// ---------------- 5) NT-GEMM down-proj (tf32 HMMA), store or scatter -------
// Block tile 128x128, warps 2x4 (64x32). 3-stage ring, one sync per k-tile.
__global__ __launch_bounds__(256, 2) void k_mlp_out_tc(
    const float* __restrict__ A0, const float* __restrict__ B0,
    float* __restrict__ out, int M, int N, int K, long sA, long sB,
    const int* __restrict__ tidx, const float* __restrict__ tw)
{
    extern __shared__ float sm[];
    float (*As)[128][AST] = (float(*)[128][AST])sm;
    float (*Bs)[128][AST] = (float(*)[128][AST])(sm + NSTG * 128 * AST);

    int e = blockIdx.z;
    const float* A = A0 + (size_t)e * sA;
    const float* B = B0 + (size_t)e * sB;

    int m0 = blockIdx.y * 128, n0 = blockIdx.x * 128;
    int tid = threadIdx.x, lane = tid & 31, warp = tid >> 5;
    int mo = (warp & 1) * 64, no = (warp >> 1) * 32;

    float acc[4][4][4] = {{{0}}};

    int ar = tid >> 2, aq = (tid & 3) * 4;
    int iters = K / BK;

#define STAGE_DN(slot, kq0)                                                      \
    do {                                                                         \
        long _k = (kq0);                                                         \
        cpa16(&As[slot][ar][aq],      A + (size_t)(m0 + ar) * K + _k + aq);      \
        cpa16(&As[slot][ar + 64][aq], A + (size_t)(m0 + ar + 64) * K + _k + aq); \
        cpa16(&Bs[slot][ar][aq],      B + (size_t)(n0 + ar) * K + _k + aq);      \
        cpa16(&Bs[slot][ar + 64][aq], B + (size_t)(n0 + ar + 64) * K + _k + aq); \
    } while (0)

    STAGE_DN(0, 0);  cpa_commit();
    STAGE_DN(1, BK); cpa_commit();

    for (int it = 0; it < iters; it++) {
        int st = it % NSTG;
        cpa_wait1();
        __syncthreads();
        if (it + 2 < iters) STAGE_DN((it + 2) % NSTG, (long)(it + 2) * BK);
        cpa_commit();

#pragma unroll
        for (int ks = 0; ks < BK; ks += 8) {
            unsigned af[4][4];
#pragma unroll
            for (int mi = 0; mi < 4; mi++) {
                int r = mo + mi * 16 + (lane >> 2);
                int c = ks + (lane & 3);
                af[mi][0] = f2tf(As[st][r][c]);
                af[mi][1] = f2tf(As[st][r + 8][c]);
                af[mi][2] = f2tf(As[st][r][c + 4]);
                af[mi][3] = f2tf(As[st][r + 8][c + 4]);
            }
#pragma unroll
            for (int ni = 0; ni < 4; ni++) {
                int bn = no + ni * 8 + (lane >> 2);
                int c = ks + (lane & 3);
                unsigned bf[2];
                bf[0] = f2tf(Bs[st][bn][c]); bf[1] = f2tf(Bs[st][bn][c + 4]);
#pragma unroll
                for (int mi = 0; mi < 4; mi++)
                    mma_tf32(acc[mi][ni], af[mi], bf, acc[mi][ni]);
            }
        }
    }
#undef STAGE_DN

    if (tidx) {
#pragma unroll
        for (int mi = 0; mi < 4; mi++) {
            int mA = m0 + mo + mi * 16 + (lane >> 2);
            int mB = mA + 8;
            int tokA = tidx[e * CC + mA]; float wA = tw[e * CC + mA];
            int tokB = tidx[e * CC + mB]; float wB = tw[e * CC + mB];
#pragma unroll
            for (int ni = 0; ni < 4; ni++) {
                int col = n0 + no + ni * 8 + (lane & 3) * 2;
                atomicAdd(&out[(size_t)tokA * N + col],     acc[mi][ni][0] * wA);
                atomicAdd(&out[(size_t)tokA * N + col + 1], acc[mi][ni][1] * wA);
                atomicAdd(&out[(size_t)tokB * N + col],     acc[mi][ni][2] * wB);
                atomicAdd(&out[(size_t)tokB * N + col + 1], acc[mi][ni][3] * wB);
            }
        }
    } else {
#pragma unroll
        for (int mi = 0; mi < 4; mi++) {
            int r0 = m0 + mo + mi * 16 + (lane >> 2);
#pragma unroll
            for (int ni = 0; ni < 4; ni++) {
                int col = n0 + no + ni * 8 + (lane & 3) * 2;
                float* p0 = out + (size_t)r0 * N + col;
                float* p1 = out + (size_t)(r0 + 8) * N + col;
                p0[0] = acc[mi][ni][0]; p0[1] = acc[mi][ni][1];
                p1[0] = acc[mi][ni][2]; p1[1] = acc[mi][ni][3];
            }
        }
    }
}

// ---------------- launch ---------------------------------------------------
extern "C" void kernel_launch(void* const* d_in, const int* in_sizes, int n_in,
                              void* d_out, int out_size) {
    const float* x  = (const float*)d_in[0];
    const float* gw = (const float*)d_in[1];
    const float* Wg = (const float*)d_in[2];
    const float* Wu = (const float*)d_in[3];
    const float* Wd = (const float*)d_in[4];
    const float* Sg = (const float*)d_in[5];
    const float* Su = (const float*)d_in[6];
    const float* Sd = (const float*)d_in[7];
    float* out = (float*)d_out;

    float *xg, *H, *Hs, *tw; int* tidx;
    cudaGetSymbolAddress((void**)&xg,   g_xg);
    cudaGetSymbolAddress((void**)&H,    g_H);
    cudaGetSymbolAddress((void**)&Hs,   g_Hs);
    cudaGetSymbolAddress((void**)&tidx, g_tidx);
    cudaGetSymbolAddress((void**)&tw,   g_tw);

    // opt-in to >48KB dynamic smem (idempotent; host-side, not a graph op)
    cudaFuncSetAttribute(k_mlp_in_tc,  cudaFuncAttributeMaxDynamicSharedMemorySize, SM_IN_BYTES);
    cudaFuncSetAttribute(k_mlp_out_tc, cudaFuncAttributeMaxDynamicSharedMemorySize, SM_DN_BYTES);

    k_gate<<<TT, 128>>>(x, gw);
    k_topk<<<EE, 512>>>();
    k_gather<<<(EE * CC * (DD / 4) + 255) / 256, 256>>>((const float4*)x);

    // expert gate/up + gelu  (M=C, N=I, K=D), batched over experts
    dim3 g1(II / 64, CC / 128, EE);
    k_mlp_in_tc<<<g1, 256, SM_IN_BYTES>>>(xg, Wg, Wu, H, CC, II, DD,
                                          (long)CC * DD, (long)II * DD, (long)CC * II);
    // shared gate/up + gelu  (M=T, N=IS, K=D)
    dim3 g2(IIS / 64, TT / 128, 1);
    k_mlp_in_tc<<<g2, 256, SM_IN_BYTES>>>(x, Sg, Su, Hs, TT, IIS, DD, 0, 0, 0);

    // shared down-proj: fully initializes out  (M=T, N=D, K=IS)
    dim3 g3(DD / 128, TT / 128, 1);
    k_mlp_out_tc<<<g3, 256, SM_DN_BYTES>>>(Hs, Sd, out, TT, DD, IIS, 0, 0, nullptr, nullptr);
    // expert down-proj + weighted scatter-add  (M=C, N=D, K=I)
    dim3 g4(DD / 128, CC / 128, EE);
    k_mlp_out_tc<<<g4, 256, SM_DN_BYTES>>>(H, Wd, out, CC, DD, II,
                                           (long)CC * II, (long)DD * II, tidx, tw);
}

// round 8
// speedup vs baseline: 1.8243x; 1.6955x over previous
#include <cuda_runtime.h>
#include <cuda_fp16.h>
#include <math.h>
#include <stdint.h>

// Problem constants
#define TT   4096
#define DD   1024
#define EE   16
#define CC   512
#define II   4096
#define IIS  2048

#define BK   32     // k-tile in fp16 elements
#define HS   40     // smem row stride in halves (32 data + 8 pad; conflict-free)

// ---------------- scratch (device globals; no allocs allowed) --------------
__device__ __align__(16) float g_scores[EE * TT];
__device__ int   g_tidx[EE * CC];
__device__ float g_tw  [EE * CC];
// fp16 operands
__device__ __align__(16) __half g_hxg[(size_t)EE * CC * DD];   // gathered tokens
__device__ __align__(16) __half g_hH [(size_t)EE * CC * II];   // expert hidden
__device__ __align__(16) __half g_hHs[(size_t)TT * IIS];       // shared hidden
__device__ __align__(16) __half g_hx [(size_t)TT * DD];        // x fp16
__device__ __align__(16) __half g_hWg[(size_t)EE * II * DD];
__device__ __align__(16) __half g_hWu[(size_t)EE * II * DD];
__device__ __align__(16) __half g_hWd[(size_t)EE * DD * II];
__device__ __align__(16) __half g_hSg[(size_t)IIS * DD];
__device__ __align__(16) __half g_hSu[(size_t)IIS * DD];
__device__ __align__(16) __half g_hSd[(size_t)DD * IIS];

// ---------------- helpers --------------------------------------------------
__device__ __forceinline__ void mma_f16(float* d, const unsigned* a, const unsigned* b,
                                        const float* c) {
    asm volatile(
        "mma.sync.aligned.m16n8k16.row.col.f32.f16.f16.f32 "
        "{%0,%1,%2,%3},{%4,%5,%6,%7},{%8,%9},{%10,%11,%12,%13};"
        : "=f"(d[0]), "=f"(d[1]), "=f"(d[2]), "=f"(d[3])
        : "r"(a[0]), "r"(a[1]), "r"(a[2]), "r"(a[3]),
          "r"(b[0]), "r"(b[1]),
          "f"(c[0]), "f"(c[1]), "f"(c[2]), "f"(c[3]));
}
__device__ __forceinline__ void cpa16(void* dst, const void* src) {
    unsigned s = (unsigned)__cvta_generic_to_shared(dst);
    asm volatile("cp.async.cg.shared.global [%0], [%1], 16;" :: "r"(s), "l"(src));
}
__device__ __forceinline__ void cpa_commit() { asm volatile("cp.async.commit_group;"); }
__device__ __forceinline__ void cpa_wait1()  { asm volatile("cp.async.wait_group 1;"); }

__device__ __forceinline__ unsigned ldh2(const __half* p) {
    return *(const unsigned*)p;
}
__device__ __forceinline__ float gelu_exact(float g) {
    return 0.5f * g * (1.f + erff(g * 0.70710678118654752f));
}

// ---------------- fp32 -> fp16 conversion ----------------------------------
__global__ void k_cvt_h(const float4* __restrict__ s, uint2* __restrict__ d, int n4) {
    for (int i = blockIdx.x * blockDim.x + threadIdx.x; i < n4; i += gridDim.x * blockDim.x) {
        float4 v = s[i];
        __half2 lo = __floats2half2_rn(v.x, v.y);
        __half2 hi = __floats2half2_rn(v.z, v.w);
        uint2 o; o.x = *(unsigned*)&lo; o.y = *(unsigned*)&hi;
        d[i] = o;
    }
}

// ---------------- gating: logits + softmax (fp32, exact) -------------------
__global__ void k_gate(const float* __restrict__ x, const float* __restrict__ gw) {
    int t = blockIdx.x;
    __shared__ float xs[DD];
    __shared__ float lg[EE];
    int tid = threadIdx.x;
    for (int k = tid; k < DD; k += 128) xs[k] = x[(size_t)t * DD + k];
    __syncthreads();
    int w = tid >> 5, lane = tid & 31;
    for (int e = w * 4; e < w * 4 + 4; e++) {
        const float* g = gw + (size_t)e * DD;
        float s = 0.f;
        for (int k = lane; k < DD; k += 32) s += xs[k] * g[k];
        for (int o = 16; o; o >>= 1) s += __shfl_down_sync(0xffffffffu, s, o);
        if (!lane) lg[e] = s;
    }
    __syncthreads();
    if (tid == 0) {
        float m = lg[0];
        for (int e = 1; e < EE; e++) m = fmaxf(m, lg[e]);
        float ex[EE]; float sum = 0.f;
        for (int e = 0; e < EE; e++) { ex[e] = expf(lg[e] - m); sum += ex[e]; }
        float inv = 1.f / sum;
        for (int e = 0; e < EE; e++) g_scores[(size_t)e * TT + t] = ex[e] * inv;
    }
}

// ---------------- per-expert top-C via bitonic sort ------------------------
__global__ void k_topk() {
    int e = blockIdx.x;
    __shared__ float v[TT];
    __shared__ int   ix[TT];
    int tid = threadIdx.x;
    for (int i = tid; i < TT; i += 512) { v[i] = g_scores[(size_t)e * TT + i]; ix[i] = i; }
    __syncthreads();
    for (int k = 2; k <= TT; k <<= 1) {
        for (int j = k >> 1; j > 0; j >>= 1) {
            for (int i = tid; i < TT; i += 512) {
                int p = i ^ j;
                if (p > i) {
                    bool desc = ((i & k) == 0);
                    float a = v[i], b = v[p];
                    if (desc ? (a < b) : (a > b)) {
                        v[i] = b; v[p] = a; int q = ix[i]; ix[i] = ix[p]; ix[p] = q;
                    }
                }
            }
            __syncthreads();
        }
    }
    for (int c = tid; c < CC; c += 512) { g_tidx[e * CC + c] = ix[c]; g_tw[e * CC + c] = v[c]; }
}

// ---------------- gather selected tokens -> fp16 ---------------------------
__global__ void k_gather(const float4* __restrict__ x4) {
    int gid = blockIdx.x * blockDim.x + threadIdx.x;
    if (gid >= EE * CC * (DD / 4)) return;
    int q = gid & (DD / 4 - 1);
    int r = gid >> 8;
    float4 v = x4[(size_t)g_tidx[r] * (DD / 4) + q];
    __half2 lo = __floats2half2_rn(v.x, v.y);
    __half2 hi = __floats2half2_rn(v.z, v.w);
    uint2 o; o.x = *(unsigned*)&lo; o.y = *(unsigned*)&hi;
    reinterpret_cast<uint2*>(g_hxg)[gid] = o;
}

// ---------------- dual NT-GEMM (fp16 HMMA) + exact GELU gate ---------------
// hH = fp16( gelu(A @ Bg^T) * (A @ Bu^T) ).  A:(M,K) rm fp16, B*:(N,K) rm fp16.
// Block tile 128x64, warps 2x4, warp tile 64x16.
__global__ __launch_bounds__(256, 2) void k_mlp_in_h(
    const __half* __restrict__ A0, const __half* __restrict__ Bg0,
    const __half* __restrict__ Bu0, __half* __restrict__ H0,
    int M, int N, int K, long sA, long sB, long sH)
{
    __shared__ __half As[2][128][HS];
    __shared__ __half Gs[2][64][HS];
    __shared__ __half Us[2][64][HS];

    int e = blockIdx.z;
    const __half* A  = A0  + (size_t)e * sA;
    const __half* Bg = Bg0 + (size_t)e * sB;
    const __half* Bu = Bu0 + (size_t)e * sB;
    __half*       H  = H0  + (size_t)e * sH;

    int m0 = blockIdx.y * 128, n0 = blockIdx.x * 64;
    int tid = threadIdx.x, lane = tid & 31, warp = tid >> 5;
    int mo = (warp & 1) * 64, no = (warp >> 1) * 16;
    int gg = lane >> 2, tt = lane & 3;

    float accG[4][2][4] = {{{0}}}, accU[4][2][4] = {{{0}}};

    // stage: A 128 rows x 64B = 512 chunks (2/thread); G,U 64 x 64B = 256 (1/thread)
    int ac0 = tid, ac1 = tid + 256;
    int ar0 = ac0 >> 2, aq0 = (ac0 & 3) * 8;   // halves offset
    int ar1 = ac1 >> 2, aq1 = (ac1 & 3) * 8;
    int br  = tid >> 2, bq = (tid & 3) * 8;

    int iters = K / BK;

#define STG_IN(slot, k0)                                                          \
    do {                                                                          \
        long _k = (k0);                                                           \
        cpa16(&As[slot][ar0][aq0], A  + (size_t)(m0 + ar0) * K + _k + aq0);       \
        cpa16(&As[slot][ar1][aq1], A  + (size_t)(m0 + ar1) * K + _k + aq1);       \
        cpa16(&Gs[slot][br][bq],   Bg + (size_t)(n0 + br) * K + _k + bq);         \
        cpa16(&Us[slot][br][bq],   Bu + (size_t)(n0 + br) * K + _k + bq);         \
    } while (0)

    STG_IN(0, 0);
    cpa_commit();

    for (int it = 0; it < iters; it++) {
        int st = it & 1;
        if (it + 1 < iters) STG_IN(1 - st, (long)(it + 1) * BK);
        cpa_commit();
        cpa_wait1();
        __syncthreads();

#pragma unroll
        for (int ks = 0; ks < BK; ks += 16) {
            unsigned af[4][4];
#pragma unroll
            for (int mi = 0; mi < 4; mi++) {
                int r = mo + mi * 16 + gg;
                af[mi][0] = ldh2(&As[st][r][ks + tt * 2]);
                af[mi][1] = ldh2(&As[st][r + 8][ks + tt * 2]);
                af[mi][2] = ldh2(&As[st][r][ks + tt * 2 + 8]);
                af[mi][3] = ldh2(&As[st][r + 8][ks + tt * 2 + 8]);
            }
#pragma unroll
            for (int ni = 0; ni < 2; ni++) {
                int bn = no + ni * 8 + gg;
                unsigned bg[2], bu[2];
                bg[0] = ldh2(&Gs[st][bn][ks + tt * 2]);
                bg[1] = ldh2(&Gs[st][bn][ks + tt * 2 + 8]);
                bu[0] = ldh2(&Us[st][bn][ks + tt * 2]);
                bu[1] = ldh2(&Us[st][bn][ks + tt * 2 + 8]);
#pragma unroll
                for (int mi = 0; mi < 4; mi++) {
                    mma_f16(accG[mi][ni], af[mi], bg, accG[mi][ni]);
                    mma_f16(accU[mi][ni], af[mi], bu, accU[mi][ni]);
                }
            }
        }
        __syncthreads();
    }
#undef STG_IN

    // epilogue: h = fp16(gelu(g) * u), stored as half2 pairs
#pragma unroll
    for (int mi = 0; mi < 4; mi++) {
        int r0 = m0 + mo + mi * 16 + gg;
#pragma unroll
        for (int ni = 0; ni < 2; ni++) {
            int col = n0 + no + ni * 8 + tt * 2;
            __half2 v0 = __floats2half2_rn(
                gelu_exact(accG[mi][ni][0]) * accU[mi][ni][0],
                gelu_exact(accG[mi][ni][1]) * accU[mi][ni][1]);
            __half2 v1 = __floats2half2_rn(
                gelu_exact(accG[mi][ni][2]) * accU[mi][ni][2],
                gelu_exact(accG[mi][ni][3]) * accU[mi][ni][3]);
            *(unsigned*)&H[(size_t)r0 * N + col]       = *(unsigned*)&v0;
            *(unsigned*)&H[(size_t)(r0 + 8) * N + col] = *(unsigned*)&v1;
        }
    }
}

// ---------------- NT-GEMM down-proj (fp16 HMMA), store or scatter ----------
// Block tile 128x128, warps 2x4, warp tile 64x32.
__global__ __launch_bounds__(256, 2) void k_mlp_out_h(
    const __half* __restrict__ A0, const __half* __restrict__ B0,
    float* __restrict__ out, int M, int N, int K, long sA, long sB,
    const int* __restrict__ tidx, const float* __restrict__ tw)
{
    __shared__ __half As[2][128][HS];
    __shared__ __half Bs[2][128][HS];

    int e = blockIdx.z;
    const __half* A = A0 + (size_t)e * sA;
    const __half* B = B0 + (size_t)e * sB;

    int m0 = blockIdx.y * 128, n0 = blockIdx.x * 128;
    int tid = threadIdx.x, lane = tid & 31, warp = tid >> 5;
    int mo = (warp & 1) * 64, no = (warp >> 1) * 32;
    int gg = lane >> 2, tt = lane & 3;

    float acc[4][4][4] = {{{0}}};

    int ac0 = tid, ac1 = tid + 256;
    int ar0 = ac0 >> 2, aq0 = (ac0 & 3) * 8;
    int ar1 = ac1 >> 2, aq1 = (ac1 & 3) * 8;

    int iters = K / BK;

#define STG_DN(slot, k0)                                                          \
    do {                                                                          \
        long _k = (k0);                                                           \
        cpa16(&As[slot][ar0][aq0], A + (size_t)(m0 + ar0) * K + _k + aq0);        \
        cpa16(&As[slot][ar1][aq1], A + (size_t)(m0 + ar1) * K + _k + aq1);        \
        cpa16(&Bs[slot][ar0][aq0], B + (size_t)(n0 + ar0) * K + _k + aq0);        \
        cpa16(&Bs[slot][ar1][aq1], B + (size_t)(n0 + ar1) * K + _k + aq1);        \
    } while (0)

    STG_DN(0, 0);
    cpa_commit();

    for (int it = 0; it < iters; it++) {
        int st = it & 1;
        if (it + 1 < iters) STG_DN(1 - st, (long)(it + 1) * BK);
        cpa_commit();
        cpa_wait1();
        __syncthreads();

#pragma unroll
        for (int ks = 0; ks < BK; ks += 16) {
            unsigned af[4][4];
#pragma unroll
            for (int mi = 0; mi < 4; mi++) {
                int r = mo + mi * 16 + gg;
                af[mi][0] = ldh2(&As[st][r][ks + tt * 2]);
                af[mi][1] = ldh2(&As[st][r + 8][ks + tt * 2]);
                af[mi][2] = ldh2(&As[st][r][ks + tt * 2 + 8]);
                af[mi][3] = ldh2(&As[st][r + 8][ks + tt * 2 + 8]);
            }
#pragma unroll
            for (int ni = 0; ni < 4; ni++) {
                int bn = no + ni * 8 + gg;
                unsigned bf[2];
                bf[0] = ldh2(&Bs[st][bn][ks + tt * 2]);
                bf[1] = ldh2(&Bs[st][bn][ks + tt * 2 + 8]);
#pragma unroll
                for (int mi = 0; mi < 4; mi++)
                    mma_f16(acc[mi][ni], af[mi], bf, acc[mi][ni]);
            }
        }
        __syncthreads();
    }
#undef STG_DN

    if (tidx) {
#pragma unroll
        for (int mi = 0; mi < 4; mi++) {
            int mA = m0 + mo + mi * 16 + gg;
            int mB = mA + 8;
            int tokA = tidx[e * CC + mA]; float wA = tw[e * CC + mA];
            int tokB = tidx[e * CC + mB]; float wB = tw[e * CC + mB];
#pragma unroll
            for (int ni = 0; ni < 4; ni++) {
                int col = n0 + no + ni * 8 + tt * 2;
                atomicAdd(&out[(size_t)tokA * N + col],     acc[mi][ni][0] * wA);
                atomicAdd(&out[(size_t)tokA * N + col + 1], acc[mi][ni][1] * wA);
                atomicAdd(&out[(size_t)tokB * N + col],     acc[mi][ni][2] * wB);
                atomicAdd(&out[(size_t)tokB * N + col + 1], acc[mi][ni][3] * wB);
            }
        }
    } else {
#pragma unroll
        for (int mi = 0; mi < 4; mi++) {
            int r0 = m0 + mo + mi * 16 + gg;
#pragma unroll
            for (int ni = 0; ni < 4; ni++) {
                int col = n0 + no + ni * 8 + tt * 2;
                float* p0 = out + (size_t)r0 * N + col;
                float* p1 = out + (size_t)(r0 + 8) * N + col;
                p0[0] = acc[mi][ni][0]; p0[1] = acc[mi][ni][1];
                p1[0] = acc[mi][ni][2]; p1[1] = acc[mi][ni][3];
            }
        }
    }
}

// ---------------- launch ---------------------------------------------------
extern "C" void kernel_launch(void* const* d_in, const int* in_sizes, int n_in,
                              void* d_out, int out_size) {
    const float* x  = (const float*)d_in[0];
    const float* gw = (const float*)d_in[1];
    const float* Wg = (const float*)d_in[2];
    const float* Wu = (const float*)d_in[3];
    const float* Wd = (const float*)d_in[4];
    const float* Sg = (const float*)d_in[5];
    const float* Su = (const float*)d_in[6];
    const float* Sd = (const float*)d_in[7];
    float* out = (float*)d_out;

    __half *hxg, *hH, *hHs, *hx, *hWg, *hWu, *hWd, *hSg, *hSu, *hSd;
    float* tw; int* tidx;
    cudaGetSymbolAddress((void**)&hxg,  g_hxg);
    cudaGetSymbolAddress((void**)&hH,   g_hH);
    cudaGetSymbolAddress((void**)&hHs,  g_hHs);
    cudaGetSymbolAddress((void**)&hx,   g_hx);
    cudaGetSymbolAddress((void**)&hWg,  g_hWg);
    cudaGetSymbolAddress((void**)&hWu,  g_hWu);
    cudaGetSymbolAddress((void**)&hWd,  g_hWd);
    cudaGetSymbolAddress((void**)&hSg,  g_hSg);
    cudaGetSymbolAddress((void**)&hSu,  g_hSu);
    cudaGetSymbolAddress((void**)&hSd,  g_hSd);
    cudaGetSymbolAddress((void**)&tidx, g_tidx);
    cudaGetSymbolAddress((void**)&tw,   g_tw);

    // fp32 -> fp16 conversions (once per launch; buys 2x MMA rate)
    k_cvt_h<<<2048, 256>>>((const float4*)Wg, (uint2*)hWg, EE * II * DD / 4);
    k_cvt_h<<<2048, 256>>>((const float4*)Wu, (uint2*)hWu, EE * II * DD / 4);
    k_cvt_h<<<2048, 256>>>((const float4*)Wd, (uint2*)hWd, EE * DD * II / 4);
    k_cvt_h<<<512, 256>>>((const float4*)Sg, (uint2*)hSg, IIS * DD / 4);
    k_cvt_h<<<512, 256>>>((const float4*)Su, (uint2*)hSu, IIS * DD / 4);
    k_cvt_h<<<512, 256>>>((const float4*)Sd, (uint2*)hSd, DD * IIS / 4);
    k_cvt_h<<<512, 256>>>((const float4*)x,  (uint2*)hx,  TT * DD / 4);

    k_gate<<<TT, 128>>>(x, gw);
    k_topk<<<EE, 512>>>();
    k_gather<<<(EE * CC * (DD / 4) + 255) / 256, 256>>>((const float4*)x);

    // expert gate/up + gelu  (M=C, N=I, K=D), batched over experts
    dim3 g1(II / 64, CC / 128, EE);
    k_mlp_in_h<<<g1, 256>>>(hxg, hWg, hWu, hH, CC, II, DD,
                            (long)CC * DD, (long)II * DD, (long)CC * II);
    // shared gate/up + gelu  (M=T, N=IS, K=D)
    dim3 g2(IIS / 64, TT / 128, 1);
    k_mlp_in_h<<<g2, 256>>>(hx, hSg, hSu, hHs, TT, IIS, DD, 0, 0, 0);

    // shared down-proj: fully initializes out  (M=T, N=D, K=IS)
    dim3 g3(DD / 128, TT / 128, 1);
    k_mlp_out_h<<<g3, 256>>>(hHs, hSd, out, TT, DD, IIS, 0, 0, nullptr, nullptr);
    // expert down-proj + weighted scatter-add  (M=C, N=D, K=I)
    dim3 g4(DD / 128, CC / 128, EE);
    k_mlp_out_h<<<g4, 256>>>(hH, hWd, out, CC, DD, II,
                             (long)CC * II, (long)DD * II, tidx, tw);
}